// round 7
// baseline (speedup 1.0000x reference)
#include <cuda_runtime.h>

#define BB 8
#define CC 64
#define DD 32
#define HH 64
#define WW 64
#define SS (DD*HH*WW)      /* 131072 spatial per batch */
#define PLANE (HH*WW)      /* 4096 */
#define S4 (SS/4)          /* 32768 */

// Scratch: channel-reduced avg/max, layout [B][D][H][W] (8 MB total).
// __device__ globals are the allocation-guard-safe scratch mechanism.
__device__ __align__(16) float g_avg[BB*SS];
__device__ __align__(16) float g_max[BB*SS];

// ---------------------------------------------------------------------------
// Pass 1: channel mean + max. One thread = 4 consecutive w elements (float4).
// Coalesced 512B per warp per c-step; c-loop unrolled for MLP.
// ---------------------------------------------------------------------------
__global__ __launch_bounds__(256) void reduce_kernel(const float* __restrict__ x) {
    int tid = blockIdx.x * blockDim.x + threadIdx.x;   // 0 .. 262143
    int b    = tid >> 15;          // tid / S4
    int off4 = tid & (S4 - 1);     // float4 index within batch-spatial

    const float4* base = reinterpret_cast<const float4*>(x)
                       + (size_t)b * CC * S4 + off4;

    float4 s = make_float4(0.f, 0.f, 0.f, 0.f);
    float4 m = make_float4(-3.402823466e38f, -3.402823466e38f,
                           -3.402823466e38f, -3.402823466e38f);

    #pragma unroll 8
    for (int c = 0; c < CC; ++c) {
        float4 v = __ldg(base + (size_t)c * S4);
        s.x += v.x; s.y += v.y; s.z += v.z; s.w += v.w;
        m.x = fmaxf(m.x, v.x); m.y = fmaxf(m.y, v.y);
        m.z = fmaxf(m.z, v.z); m.w = fmaxf(m.w, v.w);
    }

    const float inv = 1.0f / 64.0f;
    float4 a = make_float4(s.x * inv, s.y * inv, s.z * inv, s.w * inv);

    reinterpret_cast<float4*>(g_avg)[tid] = a;
    reinterpret_cast<float4*>(g_max)[tid] = m;
}

// ---------------------------------------------------------------------------
// Pass 2: 3x3x3 SAME conv (2 in-ch: avg,max -> 1 out-ch) + sigmoid.
// One thread owns (b, h, w) and a chunk of 8 d-values. Sliding-plane scheme:
// plane p contributes to outputs d = p+1 (kd=0), p (kd=1), p-1 (kd=2) via
// three rotating accumulators, so each input value is loaded exactly once
// per thread (18 LDG + 54 FFMA per d-step). Weights live in registers.
// ---------------------------------------------------------------------------
__global__ __launch_bounds__(256) void conv_kernel(const float* __restrict__ Wt,
                                                   float* __restrict__ out) {
    int g = blockIdx.x * blockDim.x + threadIdx.x;   // 0 .. 131071
    int w  = g & 63;
    int h  = (g >> 6) & 63;
    int dc = (g >> 12) & 3;     // d-chunk (8 each)
    int b  = g >> 14;

    // 54 weights -> registers (all indices compile-time after unroll)
    float wt[54];
    #pragma unroll
    for (int i = 0; i < 54; ++i) wt[i] = __ldg(Wt + i);

    const float* ga = g_avg + (size_t)b * SS;
    const float* gm = g_max + (size_t)b * SS;
    float*       ob = out   + (size_t)b * SS;

    int d0 = dc * 8;
    float a0 = 0.f, a1 = 0.f;    // accumulators for out[p-1], out[p]

    for (int p = d0 - 1; p <= d0 + 8; ++p) {
        float a2 = 0.f;          // accumulator for out[p+1]
        if (p >= 0 && p < DD) {
            const float* pa = ga + p * PLANE;
            const float* pm = gm + p * PLANE;
            #pragma unroll
            for (int kh = 0; kh < 3; ++kh) {
                int  hh  = h + kh - 1;
                bool hok = ((unsigned)hh < (unsigned)HH);
                #pragma unroll
                for (int kw = 0; kw < 3; ++kw) {
                    int  ww = w + kw - 1;
                    bool ok = hok && ((unsigned)ww < (unsigned)WW);
                    int  off = hh * WW + ww;
                    float va = ok ? __ldg(pa + off) : 0.f;
                    float vm = ok ? __ldg(pm + off) : 0.f;
                    const int i = kh * 3 + kw;
                    // ci=0 (avg) weights at wt[0..26], ci=1 (max) at wt[27..53]
                    a0 = fmaf(va, wt[18 + i], a0);        // kd=2 for out[p-1]
                    a0 = fmaf(vm, wt[27 + 18 + i], a0);
                    a1 = fmaf(va, wt[ 9 + i], a1);        // kd=1 for out[p]
                    a1 = fmaf(vm, wt[27 +  9 + i], a1);
                    a2 = fmaf(va, wt[      i], a2);       // kd=0 for out[p+1]
                    a2 = fmaf(vm, wt[27 +      i], a2);
                }
            }
        }
        if (p >= d0 + 1) {
            // out[p-1] is complete (planes p-2, p-1, p consumed)
            float v = a0;
            ob[(p - 1) * PLANE + h * WW + w] = 1.0f / (1.0f + __expf(-v));
        }
        a0 = a1;
        a1 = a2;
    }
}

extern "C" void kernel_launch(void* const* d_in, const int* in_sizes, int n_in,
                              void* d_out, int out_size) {
    const float* x  = (const float*)d_in[0];   // [8,64,32,64,64] fp32
    const float* Wt = (const float*)d_in[1];   // [1,2,3,3,3]     fp32
    float* out = (float*)d_out;                // [8,1,32,64,64]  fp32
    (void)in_sizes; (void)n_in; (void)out_size;

    // Pass 1: 262144 threads (1 per float4 of spatial)
    reduce_kernel<<<1024, 256>>>(x);
    // Pass 2: 131072 threads (1 per (b, h, w, d-chunk-of-8))
    conv_kernel<<<512, 256>>>(Wt, out);
}